// round 12
// baseline (speedup 1.0000x reference)
#include <cuda_runtime.h>
#include <cuda_fp16.h>
#include <math.h>
#include <stdint.h>

#define HH 96
#define WW 96
#define CC 256
#define FF 256
#define BB 4
#define NPIX (HH*WW)        // 9216
#define TOTPIX (BB*NPIX)    // 36864
#define NCHUNK 72           // 2304 / 32
#define NPAIR 36

// scratch: per (pixel, tap): (py, px, mask, 0)
__device__ float4 g_offmask[TOTPIX * 9];
// main weights fp16 fragment-packed: [chunk72][ks2][ntile32][lane32][reg2] (half2 as u32)
__device__ uint32_t g_kernH[NCHUNK * 2 * 32 * 32 * 2];
// om weights fp16, ks-merged: [pair36][c2][nt4][lane32][ks2*reg2] (uint4/lane; n>=27 zero)
__device__ uint32_t g_omkH[NPAIR * 2 * 4 * 32 * 4];
// fp16 copy of x (half2-packed in uint4 for alignment)
__device__ uint4 g_xh4[TOTPIX * CC / 8];

__device__ __forceinline__ uint32_t smem_u32(const void* p) {
    uint32_t a;
    asm("{ .reg .u64 t; cvta.to.shared.u64 t, %1; cvt.u32.u64 %0, t; }" : "=r"(a) : "l"(p));
    return a;
}

#define CP_ASYNC16(dst, src) \
    asm volatile("cp.async.cg.shared.global [%0], [%1], 16;" :: "r"(dst), "l"(src) : "memory")
#define CP_COMMIT() asm volatile("cp.async.commit_group;" ::: "memory")
#define CP_WAIT0()  asm volatile("cp.async.wait_group 0;" ::: "memory")

__device__ __forceinline__ void mma_f16(
    float* d, uint4 a, uint32_t b0, uint32_t b1)
{
    asm volatile(
        "mma.sync.aligned.m16n8k16.row.col.f32.f16.f16.f32 "
        "{%0,%1,%2,%3}, {%4,%5,%6,%7}, {%8,%9}, {%0,%1,%2,%3};"
        : "+f"(d[0]), "+f"(d[1]), "+f"(d[2]), "+f"(d[3])
        : "r"(a.x), "r"(a.y), "r"(a.z), "r"(a.w), "r"(b0), "r"(b1));
}

// ---------------------------------------------------------------------------
// Kernel 0: merged prep. Blocks [0,4608): x->fp16. [4608,5760): main weight
// pack. [5760,5904): om weight pack (ks-merged uint4 layout).
// ---------------------------------------------------------------------------
__global__ void __launch_bounds__(256) prep_kernel(
    const float4* __restrict__ x4, const float* __restrict__ kern,
    const float* __restrict__ omk)
{
    int blk = blockIdx.x;
    int tid = threadIdx.x;
    if (blk < 4608) {
        int idx = blk * 256 + tid;
        float4 a = x4[idx * 2];
        float4 b = x4[idx * 2 + 1];
        __half2 h0 = __floats2half2_rn(a.x, a.y);
        __half2 h1 = __floats2half2_rn(a.z, a.w);
        __half2 h2 = __floats2half2_rn(b.x, b.y);
        __half2 h3 = __floats2half2_rn(b.z, b.w);
        uint4 o;
        o.x = *(uint32_t*)&h0; o.y = *(uint32_t*)&h1;
        o.z = *(uint32_t*)&h2; o.w = *(uint32_t*)&h3;
        g_xh4[idx] = o;
    } else if (blk < 5760) {
        int idx = (blk - 4608) * 256 + tid;     // 0 .. 294911
        int reg  = idx & 1;
        int lane = (idx >> 1) & 31;
        int nt   = (idx >> 6) & 31;
        int ks   = (idx >> 11) & 1;
        int c    = idx >> 12;
        int n = nt * 8 + (lane >> 2);
        int k = c * 32 + ks * 16 + (lane & 3) * 2 + reg * 8;
        __half2 h = __floats2half2_rn(kern[k * 256 + n], kern[(k + 1) * 256 + n]);
        g_kernH[idx] = *(uint32_t*)&h;
    } else {
        int idx = (blk - 5760) * 256 + tid;     // 0 .. 36863
        int reg  = idx & 1;
        int ks   = (idx >> 1) & 1;
        int lane = (idx >> 2) & 31;
        int nt   = (idx >> 7) & 3;
        int c    = (idx >> 9) & 1;
        int pr   = idx >> 10;
        int n = nt * 8 + (lane >> 2);
        int k = pr * 64 + c * 32 + ks * 16 + (lane & 3) * 2 + reg * 8;
        float v0 = 0.f, v1 = 0.f;
        if (n < 27) {
            v0 = omk[k * 27 + n];
            v1 = omk[(k + 1) * 27 + n];
        }
        __half2 h = __floats2half2_rn(v0, v1);
        g_omkH[idx] = *(uint32_t*)&h;
    }
}

// ---------------------------------------------------------------------------
// Kernel 1: om conv fp16 HMMA (R9 structure). 576 CTAs x 128 threads,
// tile 64 px x 32 N (27 used). B uses ks-merged uint4 fragments.
// ---------------------------------------------------------------------------
__global__ void __launch_bounds__(128) om_mma_kernel(const float* __restrict__ omb)
{
    __shared__ uint32_t smA[2][2112];   // 16 blocks (4 amt x 4 ks) * 132
    __shared__ uint32_t smB[2][1024];   // 2 chunks * 512
    __shared__ float om_s[64 * 28];
    uint32_t sbB = smem_u32(&smB[0][0]);

    int tid  = threadIdx.x;
    int wid  = tid >> 5;
    int lane = tid & 31;

    int tile0 = blockIdx.x * 64;
    int b = tile0 / NPIX;
    const __half* xh = (const __half*)g_xh4 + (size_t)b * NPIX * CC;

    int o8  = lane & 7;
    int pxq = lane >> 3;
    int sks = o8 >> 1;

    int pxl[4];
    uint32_t ast[4];
    int hoq[4], woq[4];
#pragma unroll
    for (int q = 0; q < 4; ++q) {
        pxl[q] = wid * 16 + q * 4 + pxq;
        int r = pxl[q] & 15, amt = pxl[q] >> 4;
        ast[q] = (uint32_t)(amt * 4 + sks) * 132u
               + (uint32_t)((r & 7) * 16)
               + (uint32_t)((r >= 8) ? 1 : 0)
               + (uint32_t)((o8 & 1) ? 2 : 0);
        int pp = tile0 + pxl[q];
        hoq[q] = (pp % NPIX) / WW;
        woq[q] = pp % WW;
    }

    float acc[4][4];
#pragma unroll
    for (int j = 0; j < 4; ++j)
#pragma unroll
        for (int q = 0; q < 4; ++q) acc[j][q] = 0.f;

    uint32_t rofs[4];
    bool rval[4];

    auto tapsetup = [&](int tap) {
        int ky = tap / 3, kx = tap % 3;
#pragma unroll
        for (int q = 0; q < 4; ++q) {
            int y = hoq[q] - 1 + ky, xx = woq[q] - 1 + kx;
            rval[q] = (y >= 0 && y < HH && xx >= 0 && xx < WW);
            rofs[q] = (uint32_t)((y * WW + xx) * CC);
        }
    };

    auto cpasyncB = [&](int pr, int s) {
        const uint4* src = (const uint4*)g_omkH + (size_t)pr * 256;
        uint32_t bdst = sbB + (uint32_t)s * 4096;
        CP_ASYNC16(bdst + (uint32_t)tid * 16, (const void*)(src + tid));
        CP_ASYNC16(bdst + (uint32_t)(tid + 128) * 16, (const void*)(src + tid + 128));
        CP_COMMIT();
    };

    auto loadv = [&](int pr, uint4* v) {
        uint32_t chb = (uint32_t)((pr & 3) * 64 + o8 * 8);
#pragma unroll
        for (int q = 0; q < 4; ++q) {
            if (rval[q]) v[q] = *(const uint4*)(xh + rofs[q] + chb);
            else         v[q] = make_uint4(0u, 0u, 0u, 0u);
        }
    };

    auto storev = [&](int q, uint4 v, uint32_t* An) {
        An[ast[q]]      = v.x;
        An[ast[q] + 4]  = v.y;
        An[ast[q] + 8]  = v.z;
        An[ast[q] + 12] = v.w;
    };

    // per chunk c (0/1): af for ks0/ks1, B uint4 covers both ks
    auto domma = [&](int s, int c) {
        const uint32_t* As = smA[s];
        const uint32_t* Bc = smB[s] + c * 512;
        uint4 af0 = *(const uint4*)(As + (uint32_t)(wid * 4 + c * 2 + 0) * 132u + (uint32_t)lane * 4u);
        uint4 af1 = *(const uint4*)(As + (uint32_t)(wid * 4 + c * 2 + 1) * 132u + (uint32_t)lane * 4u);
#pragma unroll
        for (int nt = 0; nt < 4; ++nt) {
            uint4 bf = *(const uint4*)(Bc + ((uint32_t)(nt * 32) + lane) * 4u);
            mma_f16(acc[nt], af0, bf.x, bf.y);
            mma_f16(acc[nt], af1, bf.z, bf.w);
        }
    };

    // prologue: fill pair 0
    {
        tapsetup(0);
        uint4 v[4];
        loadv(0, v);
#pragma unroll
        for (int q = 0; q < 4; ++q) storev(q, v[q], smA[0]);
        cpasyncB(0, 0);
        CP_WAIT0();
        __syncthreads();
    }

    for (int it = 0; it < NPAIR; ++it) {
        int s = it & 1;
        int nxt = it + 1;
        bool have = nxt < NPAIR;
        uint4 v[4];
        if (have) {
            if ((nxt & 3) == 0) tapsetup(nxt >> 2);
            loadv(nxt, v);
            cpasyncB(nxt, s ^ 1);
        }
        domma(s, 0);
        if (have) { storev(0, v[0], smA[s ^ 1]); storev(1, v[1], smA[s ^ 1]); }
        domma(s, 1);
        if (have) { storev(2, v[2], smA[s ^ 1]); storev(3, v[3], smA[s ^ 1]); }
        CP_WAIT0();
        __syncthreads();
    }

    // ---- epilogue: acc (+bias) -> om_s ----
    {
        int qrow = lane >> 2;
        int qcol = (lane & 3) * 2;
        int row = wid * 16 + qrow;
#pragma unroll
        for (int nt = 0; nt < 4; ++nt) {
            int col = nt * 8 + qcol;
            if (col < 27) {
                float ob = omb[col];
                om_s[row * 28 + col]       = acc[nt][0] + ob;
                om_s[(row + 8) * 28 + col] = acc[nt][2] + ob;
            }
            if (col + 1 < 27) {
                float ob = omb[col + 1];
                om_s[row * 28 + col + 1]       = acc[nt][1] + ob;
                om_s[(row + 8) * 28 + col + 1] = acc[nt][3] + ob;
            }
        }
    }
    __syncthreads();

    // ---- offsets/mask -> g_offmask ----
    if (tid < 64) {
        int px = tid;
        int pp = tile0 + px;
        int ho = (pp % NPIX) / WW;
        int wo = pp % WW;
#pragma unroll
        for (int k = 0; k < 9; ++k) {
            float dy = om_s[px * 28 + 2 * k];
            float dx = om_s[px * 28 + 2 * k + 1];
            float m  = 2.f / (1.f + expf(-om_s[px * 28 + 18 + k]));
            int ky = k / 3, kx = k % 3;
            float py  = (float)(ho - 1 + ky) + dy;
            float pxx = (float)(wo - 1 + kx) + dx;
            g_offmask[pp * 9 + k] = make_float4(py, pxx, m, 0.f);
        }
    }
}

// ---------------------------------------------------------------------------
// Kernel 2: fused bilinear sampling (fp16 x) + HMMA fp16 GEMM, chunk-pair
// stages. 288 CTAs x 512 threads. (R9 proven version, verbatim)
// ---------------------------------------------------------------------------
#define A_STAGE 4224                 // u32: 32 blocks (8 amt x 4 ks) * 132
#define B_STAGE 8192                 // u32: 2 chunks * 16 KB
#define SMEM_U32 (2*A_STAGE + 2*B_STAGE)

__global__ void __launch_bounds__(512, 1) dcn_mma_kernel(
    const float* __restrict__ bias, float* __restrict__ out)
{
    extern __shared__ uint32_t sm[];
    uint32_t* AsArr[2] = { sm, sm + A_STAGE };
    uint32_t* BsArr[2] = { sm + 2*A_STAGE, sm + 2*A_STAGE + B_STAGE };
    uint32_t sbB = smem_u32(sm + 2*A_STAGE);

    int tid  = threadIdx.x;
    int wid  = tid >> 5;
    int lane = tid & 31;

    int tile0 = blockIdx.x * 128;
    int b = tile0 / NPIX;
    const __half* xh = (const __half*)g_xh4 + (size_t)b * NPIX * CC;

    int o8  = lane & 7;
    int pxq = lane >> 3;
    int pxl[2] = { wid * 8 + pxq, wid * 8 + 4 + pxq };
    int sks = o8 >> 1;

    uint32_t ast[2];
#pragma unroll
    for (int q = 0; q < 2; ++q) {
        int r   = pxl[q] & 15;
        int amt = pxl[q] >> 4;
        ast[q] = (uint32_t)(amt * 4 + sks) * 132u
               + (uint32_t)((r & 7) * 16)
               + (uint32_t)((r >= 8) ? 1 : 0)
               + (uint32_t)((o8 & 1) ? 2 : 0);
    }

    int wm = wid & 3;
    int wn = wid >> 2;

    float acc[2][8][4];
#pragma unroll
    for (int i = 0; i < 2; ++i)
#pragma unroll
        for (int j = 0; j < 8; ++j)
#pragma unroll
            for (int q = 0; q < 4; ++q) acc[i][j][q] = 0.f;

    float wgt[2][4];
    uint32_t ofs[2][4];

    auto tapsetup = [&](int tap) {
#pragma unroll
        for (int q = 0; q < 2; ++q) {
            float4 om = g_offmask[(size_t)(tile0 + pxl[q]) * 9 + tap];
            float fy0 = floorf(om.x), fx0 = floorf(om.y);
            int iy0 = (int)fy0, ix0 = (int)fx0;
            float fy = om.x - fy0, fx = om.y - fx0;
            float m = om.z;
            float w00 = (1.f - fy) * (1.f - fx) * m;
            float w01 = (1.f - fy) * fx * m;
            float w10 = fy * (1.f - fx) * m;
            float w11 = fy * fx * m;
            if (iy0 < 0  || iy0 >= HH)     { w00 = 0.f; w01 = 0.f; }
            if (iy0 < -1 || iy0 >= HH - 1) { w10 = 0.f; w11 = 0.f; }
            if (ix0 < 0  || ix0 >= WW)     { w00 = 0.f; w10 = 0.f; }
            if (ix0 < -1 || ix0 >= WW - 1) { w01 = 0.f; w11 = 0.f; }
            int y0c = min(max(iy0, 0), HH - 1);
            int y1c = min(max(iy0 + 1, 0), HH - 1);
            int x0c = min(max(ix0, 0), WW - 1);
            int x1c = min(max(ix0 + 1, 0), WW - 1);
            wgt[q][0] = w00; wgt[q][1] = w01; wgt[q][2] = w10; wgt[q][3] = w11;
            ofs[q][0] = (uint32_t)((y0c * WW + x0c) * CC);
            ofs[q][1] = (uint32_t)((y0c * WW + x1c) * CC);
            ofs[q][2] = (uint32_t)((y1c * WW + x0c) * CC);
            ofs[q][3] = (uint32_t)((y1c * WW + x1c) * CC);
        }
    };

    auto cpasyncB = [&](int pr, int s) {
        const float4* src = (const float4*)g_kernH + (size_t)pr * 2048;
        uint32_t bdst = sbB + (uint32_t)s * (B_STAGE * 4);
#pragma unroll
        for (int i = 0; i < 4; ++i)
            CP_ASYNC16(bdst + (uint32_t)(tid + i * 512) * 16,
                       (const void*)(src + tid + i * 512));
        CP_COMMIT();
    };

    auto combine_store = [&](int q, uint4 v0, uint4 v1, uint4 v2, uint4 v3,
                             uint32_t* An) {
        float r[8];
        const __half2* h0 = (const __half2*)&v0;
        const __half2* h1 = (const __half2*)&v1;
        const __half2* h2 = (const __half2*)&v2;
        const __half2* h3 = (const __half2*)&v3;
#pragma unroll
        for (int j = 0; j < 4; ++j) {
            float2 f0 = __half22float2(h0[j]);
            float2 f1 = __half22float2(h1[j]);
            float2 f2 = __half22float2(h2[j]);
            float2 f3 = __half22float2(h3[j]);
            r[2*j]   = wgt[q][0]*f0.x + wgt[q][1]*f1.x + wgt[q][2]*f2.x + wgt[q][3]*f3.x;
            r[2*j+1] = wgt[q][0]*f0.y + wgt[q][1]*f1.y + wgt[q][2]*f2.y + wgt[q][3]*f3.y;
        }
#pragma unroll
        for (int j = 0; j < 4; ++j) {
            __half2 h = __floats2half2_rn(r[2*j], r[2*j+1]);
            An[ast[q] + j * 4] = *(uint32_t*)&h;
        }
    };

    auto domma = [&](int s, int kss) {
        const uint32_t* As = AsArr[s];
        const uint32_t* Bs = BsArr[s];
        uint4 af[2];
#pragma unroll
        for (int mt = 0; mt < 2; ++mt) {
            int amt = wm * 2 + mt;
            af[mt] = *(const uint4*)(As + (uint32_t)(amt * 4 + kss) * 132u + (uint32_t)lane * 4u);
        }
        const uint32_t* Bc = Bs + (kss >> 1) * 4096;
        int ks = kss & 1;
#pragma unroll
        for (int nt = 0; nt < 8; ++nt) {
            int ntg = wn * 8 + nt;
            const uint32_t* bp = Bc + ((uint32_t)(ks * 32 + ntg) * 32 + lane) * 2u;
            uint32_t b0 = bp[0], b1 = bp[1];
            mma_f16(acc[0][nt], af[0], b0, b1);
            mma_f16(acc[1][nt], af[1], b0, b1);
        }
    };

    // prologue: fill pair 0
    tapsetup(0);
#pragma unroll
    for (int q = 0; q < 2; ++q) {
        uint32_t chb = (uint32_t)(o8 * 8);
        uint4 v0 = *(const uint4*)(xh + ofs[q][0] + chb);
        uint4 v1 = *(const uint4*)(xh + ofs[q][1] + chb);
        uint4 v2 = *(const uint4*)(xh + ofs[q][2] + chb);
        uint4 v3 = *(const uint4*)(xh + ofs[q][3] + chb);
        combine_store(q, v0, v1, v2, v3, AsArr[0]);
    }
    cpasyncB(0, 0);
    CP_WAIT0();
    __syncthreads();

    for (int it = 0; it < NPAIR; ++it) {
        int s = it & 1;
        int nxt = it + 1;
        bool have = nxt < NPAIR;
        uint32_t chb = 0;
        uint4 v0, v1, v2, v3;

        if (have) {
            if ((nxt & 3) == 0) tapsetup(nxt >> 2);
            chb = (uint32_t)((nxt & 3) * 64 + o8 * 8);
            v0 = *(const uint4*)(xh + ofs[0][0] + chb);
            v1 = *(const uint4*)(xh + ofs[0][1] + chb);
            v2 = *(const uint4*)(xh + ofs[0][2] + chb);
            v3 = *(const uint4*)(xh + ofs[0][3] + chb);
            cpasyncB(nxt, s ^ 1);
        }

        domma(s, 0);

        if (have) {
            combine_store(0, v0, v1, v2, v3, AsArr[s ^ 1]);
            v0 = *(const uint4*)(xh + ofs[1][0] + chb);
            v1 = *(const uint4*)(xh + ofs[1][1] + chb);
            v2 = *(const uint4*)(xh + ofs[1][2] + chb);
            v3 = *(const uint4*)(xh + ofs[1][3] + chb);
        }

        domma(s, 1);

        if (have) combine_store(1, v0, v1, v2, v3, AsArr[s ^ 1]);

        domma(s, 2);
        domma(s, 3);

        CP_WAIT0();
        __syncthreads();
    }

    // ---- epilogue: acc -> global with bias ----
    {
        int col0 = wn * 64;
        int qrow = lane >> 2;
        int qcol = (lane & 3) * 2;
        float2 bv[8];
#pragma unroll
        for (int nt = 0; nt < 8; ++nt)
            bv[nt] = *(const float2*)(bias + col0 + nt * 8 + qcol);
#pragma unroll
        for (int mt = 0; mt < 2; ++mt) {
            int row = tile0 + wm * 32 + mt * 16 + qrow;
#pragma unroll
            for (int nt = 0; nt < 8; ++nt) {
                int col = col0 + nt * 8 + qcol;
                float2 lo, hi;
                lo.x = acc[mt][nt][0] + bv[nt].x;
                lo.y = acc[mt][nt][1] + bv[nt].y;
                hi.x = acc[mt][nt][2] + bv[nt].x;
                hi.y = acc[mt][nt][3] + bv[nt].y;
                *(float2*)(out + (size_t)row * FF + col)       = lo;
                *(float2*)(out + (size_t)(row + 8) * FF + col) = hi;
            }
        }
    }
}

extern "C" void kernel_launch(void* const* d_in, const int* in_sizes, int n_in,
                              void* d_out, int out_size)
{
    const float* x    = (const float*)d_in[0];  // [4,96,96,256]
    const float* omk  = (const float*)d_in[1];  // [3,3,256,27]
    const float* omb  = (const float*)d_in[2];  // [27]
    const float* kern = (const float*)d_in[3];  // [2304,256]
    const float* bias = (const float*)d_in[4];  // [256]
    float* out = (float*)d_out;                 // [36864,256]

    cudaFuncSetAttribute(dcn_mma_kernel,
                         cudaFuncAttributeMaxDynamicSharedMemorySize, SMEM_U32 * 4);

    prep_kernel<<<5904, 256>>>((const float4*)x, kern, omk);
    om_mma_kernel<<<TOTPIX / 64, 128>>>(omb);
    dcn_mma_kernel<<<TOTPIX / 128, 512, SMEM_U32 * 4>>>(bias, out);
}

// round 13
// speedup vs baseline: 1.1099x; 1.1099x over previous
#include <cuda_runtime.h>
#include <cuda_fp16.h>
#include <math.h>
#include <stdint.h>

#define HH 96
#define WW 96
#define CC 256
#define FF 256
#define BB 4
#define NPIX (HH*WW)        // 9216
#define TOTPIX (BB*NPIX)    // 36864
#define NCHUNK 72           // 2304 / 32
#define NPAIR 36

// scratch: per (pixel, tap): (py, px, mask, 0)
__device__ float4 g_offmask[TOTPIX * 9];
// main weights fp16 fragment-packed: [chunk72][ks2][ntile32][lane32][reg2] (half2 as u32)
__device__ uint32_t g_kernH[NCHUNK * 2 * 32 * 32 * 2];
// om weights fp16 fragment-packed: [chunk72][ks2][ntile4][lane32][reg2] (n>=27 zero)
__device__ uint32_t g_omkH[NCHUNK * 2 * 4 * 32 * 2];
// fp16 copy of x (half2-packed in uint4 for alignment)
__device__ uint4 g_xh4[TOTPIX * CC / 8];

__device__ __forceinline__ uint32_t smem_u32(const void* p) {
    uint32_t a;
    asm("{ .reg .u64 t; cvta.to.shared.u64 t, %1; cvt.u32.u64 %0, t; }" : "=r"(a) : "l"(p));
    return a;
}

#define CP_ASYNC16(dst, src) \
    asm volatile("cp.async.cg.shared.global [%0], [%1], 16;" :: "r"(dst), "l"(src) : "memory")
#define CP_COMMIT() asm volatile("cp.async.commit_group;" ::: "memory")
#define CP_WAIT0()  asm volatile("cp.async.wait_group 0;" ::: "memory")

__device__ __forceinline__ void mma_f16(
    float* d, uint4 a, uint2 b)
{
    asm volatile(
        "mma.sync.aligned.m16n8k16.row.col.f32.f16.f16.f32 "
        "{%0,%1,%2,%3}, {%4,%5,%6,%7}, {%8,%9}, {%0,%1,%2,%3};"
        : "+f"(d[0]), "+f"(d[1]), "+f"(d[2]), "+f"(d[3])
        : "r"(a.x), "r"(a.y), "r"(a.z), "r"(a.w), "r"(b.x), "r"(b.y));
}

// ---------------------------------------------------------------------------
// Kernel 0: merged prep. Blocks [0,4608): x->fp16. [4608,5760): main weight
// pack. [5760,5904): om weight pack (R9 layout).
// ---------------------------------------------------------------------------
__global__ void __launch_bounds__(256) prep_kernel(
    const float4* __restrict__ x4, const float* __restrict__ kern,
    const float* __restrict__ omk)
{
    int blk = blockIdx.x;
    int tid = threadIdx.x;
    if (blk < 4608) {
        int idx = blk * 256 + tid;
        float4 a = x4[idx * 2];
        float4 b = x4[idx * 2 + 1];
        __half2 h0 = __floats2half2_rn(a.x, a.y);
        __half2 h1 = __floats2half2_rn(a.z, a.w);
        __half2 h2 = __floats2half2_rn(b.x, b.y);
        __half2 h3 = __floats2half2_rn(b.z, b.w);
        uint4 o;
        o.x = *(uint32_t*)&h0; o.y = *(uint32_t*)&h1;
        o.z = *(uint32_t*)&h2; o.w = *(uint32_t*)&h3;
        g_xh4[idx] = o;
    } else if (blk < 5760) {
        int idx = (blk - 4608) * 256 + tid;     // 0 .. 294911
        int reg  = idx & 1;
        int lane = (idx >> 1) & 31;
        int nt   = (idx >> 6) & 31;
        int ks   = (idx >> 11) & 1;
        int c    = idx >> 12;
        int n = nt * 8 + (lane >> 2);
        int k = c * 32 + ks * 16 + (lane & 3) * 2 + reg * 8;
        __half2 h = __floats2half2_rn(kern[k * 256 + n], kern[(k + 1) * 256 + n]);
        g_kernH[idx] = *(uint32_t*)&h;
    } else {
        int idx = (blk - 5760) * 256 + tid;     // 0 .. 36863
        int reg  = idx & 1;
        int lane = (idx >> 1) & 31;
        int nt   = (idx >> 6) & 3;
        int ks   = (idx >> 8) & 1;
        int c    = idx >> 9;
        int n = nt * 8 + (lane >> 2);
        int k = c * 32 + ks * 16 + (lane & 3) * 2 + reg * 8;
        float v0 = 0.f, v1 = 0.f;
        if (n < 27) {
            v0 = omk[k * 27 + n];
            v1 = omk[(k + 1) * 27 + n];
        }
        __half2 h = __floats2half2_rn(v0, v1);
        g_omkH[idx] = *(uint32_t*)&h;
    }
}

// ---------------------------------------------------------------------------
// Kernel 1: om conv fp16 HMMA (R9 verbatim). 576 CTAs x 128 threads.
// Tile 64 px x 32 N (27 used). Chunk-pair stages.
// ---------------------------------------------------------------------------
__global__ void __launch_bounds__(128) om_mma_kernel(const float* __restrict__ omb)
{
    __shared__ uint32_t smA[2][2112];   // 16 blocks (4 amt x 4 ks) * 132
    __shared__ uint32_t smB[2][1024];   // 2 chunks * 512
    __shared__ float om_s[64 * 28];
    uint32_t sbB = smem_u32(&smB[0][0]);

    int tid  = threadIdx.x;
    int wid  = tid >> 5;
    int lane = tid & 31;

    int tile0 = blockIdx.x * 64;
    int b = tile0 / NPIX;
    const __half* xh = (const __half*)g_xh4 + (size_t)b * NPIX * CC;

    int o8  = lane & 7;
    int pxq = lane >> 3;
    int sks = o8 >> 1;

    int pxl[4];
    uint32_t ast[4];
    int hoq[4], woq[4];
#pragma unroll
    for (int q = 0; q < 4; ++q) {
        pxl[q] = wid * 16 + q * 4 + pxq;
        int r = pxl[q] & 15, amt = pxl[q] >> 4;
        ast[q] = (uint32_t)(amt * 4 + sks) * 132u
               + (uint32_t)((r & 7) * 16)
               + (uint32_t)((r >= 8) ? 1 : 0)
               + (uint32_t)((o8 & 1) ? 2 : 0);
        int pp = tile0 + pxl[q];
        hoq[q] = (pp % NPIX) / WW;
        woq[q] = pp % WW;
    }

    float acc[4][4];
#pragma unroll
    for (int j = 0; j < 4; ++j)
#pragma unroll
        for (int q = 0; q < 4; ++q) acc[j][q] = 0.f;

    uint32_t rofs[4];
    bool rval[4];

    auto tapsetup = [&](int tap) {
        int ky = tap / 3, kx = tap % 3;
#pragma unroll
        for (int q = 0; q < 4; ++q) {
            int y = hoq[q] - 1 + ky, xx = woq[q] - 1 + kx;
            rval[q] = (y >= 0 && y < HH && xx >= 0 && xx < WW);
            rofs[q] = (uint32_t)((y * WW + xx) * CC);
        }
    };

    auto cpasyncB = [&](int pr, int s) {
        const uint4* src = (const uint4*)g_omkH + (size_t)pr * 256;
        uint32_t bdst = sbB + (uint32_t)s * 4096;
        CP_ASYNC16(bdst + (uint32_t)tid * 16, (const void*)(src + tid));
        CP_ASYNC16(bdst + (uint32_t)(tid + 128) * 16, (const void*)(src + tid + 128));
        CP_COMMIT();
    };

    auto loadv = [&](int pr, uint4* v) {
        uint32_t chb = (uint32_t)((pr & 3) * 64 + o8 * 8);
#pragma unroll
        for (int q = 0; q < 4; ++q) {
            if (rval[q]) v[q] = *(const uint4*)(xh + rofs[q] + chb);
            else         v[q] = make_uint4(0u, 0u, 0u, 0u);
        }
    };

    auto storev = [&](int q, uint4 v, uint32_t* An) {
        An[ast[q]]      = v.x;
        An[ast[q] + 4]  = v.y;
        An[ast[q] + 8]  = v.z;
        An[ast[q] + 12] = v.w;
    };

    auto domma = [&](int s, int kss) {
        const uint32_t* As = smA[s];
        const uint32_t* Bs = smB[s];
        uint4 af = *(const uint4*)(As + (uint32_t)(wid * 4 + kss) * 132u + (uint32_t)lane * 4u);
        const uint32_t* Bc = Bs + (kss >> 1) * 512;
        int ks = kss & 1;
#pragma unroll
        for (int nt = 0; nt < 4; ++nt) {
            uint2 bf = *(const uint2*)(Bc + ((uint32_t)(ks * 4 + nt) * 32 + lane) * 2u);
            mma_f16(acc[nt], af, bf);
        }
    };

    // prologue: fill pair 0
    {
        tapsetup(0);
        uint4 v[4];
        loadv(0, v);
#pragma unroll
        for (int q = 0; q < 4; ++q) storev(q, v[q], smA[0]);
        cpasyncB(0, 0);
        CP_WAIT0();
        __syncthreads();
    }

    for (int it = 0; it < NPAIR; ++it) {
        int s = it & 1;
        int nxt = it + 1;
        bool have = nxt < NPAIR;
        uint4 v[4];
        if (have) {
            if ((nxt & 3) == 0) tapsetup(nxt >> 2);
            loadv(nxt, v);
            cpasyncB(nxt, s ^ 1);
        }
        domma(s, 0);
        if (have) { storev(0, v[0], smA[s ^ 1]); storev(1, v[1], smA[s ^ 1]); }
        domma(s, 1);
        if (have) { storev(2, v[2], smA[s ^ 1]); storev(3, v[3], smA[s ^ 1]); }
        domma(s, 2);
        domma(s, 3);
        CP_WAIT0();
        __syncthreads();
    }

    // ---- epilogue: acc (+bias) -> om_s ----
    {
        int qrow = lane >> 2;
        int qcol = (lane & 3) * 2;
        int row = wid * 16 + qrow;
#pragma unroll
        for (int nt = 0; nt < 4; ++nt) {
            int col = nt * 8 + qcol;
            if (col < 27) {
                float ob = omb[col];
                om_s[row * 28 + col]       = acc[nt][0] + ob;
                om_s[(row + 8) * 28 + col] = acc[nt][2] + ob;
            }
            if (col + 1 < 27) {
                float ob = omb[col + 1];
                om_s[row * 28 + col + 1]       = acc[nt][1] + ob;
                om_s[(row + 8) * 28 + col + 1] = acc[nt][3] + ob;
            }
        }
    }
    __syncthreads();

    // ---- offsets/mask -> g_offmask ----
    if (tid < 64) {
        int px = tid;
        int pp = tile0 + px;
        int ho = (pp % NPIX) / WW;
        int wo = pp % WW;
#pragma unroll
        for (int k = 0; k < 9; ++k) {
            float dy = om_s[px * 28 + 2 * k];
            float dx = om_s[px * 28 + 2 * k + 1];
            float m  = 2.f / (1.f + expf(-om_s[px * 28 + 18 + k]));
            int ky = k / 3, kx = k % 3;
            float py  = (float)(ho - 1 + ky) + dy;
            float pxx = (float)(wo - 1 + kx) + dx;
            g_offmask[pp * 9 + k] = make_float4(py, pxx, m, 0.f);
        }
    }
}

// ---------------------------------------------------------------------------
// Kernel 2: fused bilinear sampling (fp16 x) + HMMA fp16 GEMM, chunk-pair
// stages. 288 CTAs x 512 threads. (R9 verbatim)
// ---------------------------------------------------------------------------
#define A_STAGE 4224                 // u32: 32 blocks (8 amt x 4 ks) * 132
#define B_STAGE 8192                 // u32: 2 chunks * 16 KB
#define SMEM_U32 (2*A_STAGE + 2*B_STAGE)

__global__ void __launch_bounds__(512, 1) dcn_mma_kernel(
    const float* __restrict__ bias, float* __restrict__ out)
{
    extern __shared__ uint32_t sm[];
    uint32_t* AsArr[2] = { sm, sm + A_STAGE };
    uint32_t* BsArr[2] = { sm + 2*A_STAGE, sm + 2*A_STAGE + B_STAGE };
    uint32_t sbB = smem_u32(sm + 2*A_STAGE);

    int tid  = threadIdx.x;
    int wid  = tid >> 5;
    int lane = tid & 31;

    int tile0 = blockIdx.x * 128;
    int b = tile0 / NPIX;
    const __half* xh = (const __half*)g_xh4 + (size_t)b * NPIX * CC;

    int o8  = lane & 7;
    int pxq = lane >> 3;
    int pxl[2] = { wid * 8 + pxq, wid * 8 + 4 + pxq };
    int sks = o8 >> 1;

    uint32_t ast[2];
#pragma unroll
    for (int q = 0; q < 2; ++q) {
        int r   = pxl[q] & 15;
        int amt = pxl[q] >> 4;
        ast[q] = (uint32_t)(amt * 4 + sks) * 132u
               + (uint32_t)((r & 7) * 16)
               + (uint32_t)((r >= 8) ? 1 : 0)
               + (uint32_t)((o8 & 1) ? 2 : 0);
    }

    int wm = wid & 3;
    int wn = wid >> 2;

    float acc[2][8][4];
#pragma unroll
    for (int i = 0; i < 2; ++i)
#pragma unroll
        for (int j = 0; j < 8; ++j)
#pragma unroll
            for (int q = 0; q < 4; ++q) acc[i][j][q] = 0.f;

    float wgt[2][4];
    uint32_t ofs[2][4];

    auto tapsetup = [&](int tap) {
#pragma unroll
        for (int q = 0; q < 2; ++q) {
            float4 om = g_offmask[(size_t)(tile0 + pxl[q]) * 9 + tap];
            float fy0 = floorf(om.x), fx0 = floorf(om.y);
            int iy0 = (int)fy0, ix0 = (int)fx0;
            float fy = om.x - fy0, fx = om.y - fx0;
            float m = om.z;
            float w00 = (1.f - fy) * (1.f - fx) * m;
            float w01 = (1.f - fy) * fx * m;
            float w10 = fy * (1.f - fx) * m;
            float w11 = fy * fx * m;
            if (iy0 < 0  || iy0 >= HH)     { w00 = 0.f; w01 = 0.f; }
            if (iy0 < -1 || iy0 >= HH - 1) { w10 = 0.f; w11 = 0.f; }
            if (ix0 < 0  || ix0 >= WW)     { w00 = 0.f; w10 = 0.f; }
            if (ix0 < -1 || ix0 >= WW - 1) { w01 = 0.f; w11 = 0.f; }
            int y0c = min(max(iy0, 0), HH - 1);
            int y1c = min(max(iy0 + 1, 0), HH - 1);
            int x0c = min(max(ix0, 0), WW - 1);
            int x1c = min(max(ix0 + 1, 0), WW - 1);
            wgt[q][0] = w00; wgt[q][1] = w01; wgt[q][2] = w10; wgt[q][3] = w11;
            ofs[q][0] = (uint32_t)((y0c * WW + x0c) * CC);
            ofs[q][1] = (uint32_t)((y0c * WW + x1c) * CC);
            ofs[q][2] = (uint32_t)((y1c * WW + x0c) * CC);
            ofs[q][3] = (uint32_t)((y1c * WW + x1c) * CC);
        }
    };

    auto cpasyncB = [&](int pr, int s) {
        const float4* src = (const float4*)g_kernH + (size_t)pr * 2048;
        uint32_t bdst = sbB + (uint32_t)s * (B_STAGE * 4);
#pragma unroll
        for (int i = 0; i < 4; ++i)
            CP_ASYNC16(bdst + (uint32_t)(tid + i * 512) * 16,
                       (const void*)(src + tid + i * 512));
        CP_COMMIT();
    };

    auto combine_store = [&](int q, uint4 v0, uint4 v1, uint4 v2, uint4 v3,
                             uint32_t* An) {
        float r[8];
        const __half2* h0 = (const __half2*)&v0;
        const __half2* h1 = (const __half2*)&v1;
        const __half2* h2 = (const __half2*)&v2;
        const __half2* h3 = (const __half2*)&v3;
#pragma unroll
        for (int j = 0; j < 4; ++j) {
            float2 f0 = __half22float2(h0[j]);
            float2 f1 = __half22float2(h1[j]);
            float2 f2 = __half22float2(h2[j]);
            float2 f3 = __half22float2(h3[j]);
            r[2*j]   = wgt[q][0]*f0.x + wgt[q][1]*f1.x + wgt[q][2]*f2.x + wgt[q][3]*f3.x;
            r[2*j+1] = wgt[q][0]*f0.y + wgt[q][1]*f1.y + wgt[q][2]*f2.y + wgt[q][3]*f3.y;
        }
#pragma unroll
        for (int j = 0; j < 4; ++j) {
            __half2 h = __floats2half2_rn(r[2*j], r[2*j+1]);
            An[ast[q] + j * 4] = *(uint32_t*)&h;
        }
    };

    auto domma = [&](int s, int kss) {
        const uint32_t* As = AsArr[s];
        const uint32_t* Bs = BsArr[s];
        uint4 af[2];
#pragma unroll
        for (int mt = 0; mt < 2; ++mt) {
            int amt = wm * 2 + mt;
            af[mt] = *(const uint4*)(As + (uint32_t)(amt * 4 + kss) * 132u + (uint32_t)lane * 4u);
        }
        const uint32_t* Bc = Bs + (kss >> 1) * 4096;
        int ks = kss & 1;
#pragma unroll
        for (int nt = 0; nt < 8; ++nt) {
            int ntg = wn * 8 + nt;
            uint2 bf = *(const uint2*)(Bc + ((uint32_t)(ks * 32 + ntg) * 32 + lane) * 2u);
            mma_f16(acc[0][nt], af[0], bf);
            mma_f16(acc[1][nt], af[1], bf);
        }
    };

    // prologue: fill pair 0
    tapsetup(0);
#pragma unroll
    for (int q = 0; q < 2; ++q) {
        uint32_t chb = (uint32_t)(o8 * 8);
        uint4 v0 = *(const uint4*)(xh + ofs[q][0] + chb);
        uint4 v1 = *(const uint4*)(xh + ofs[q][1] + chb);
        uint4 v2 = *(const uint4*)(xh + ofs[q][2] + chb);
        uint4 v3 = *(const uint4*)(xh + ofs[q][3] + chb);
        combine_store(q, v0, v1, v2, v3, AsArr[0]);
    }
    cpasyncB(0, 0);
    CP_WAIT0();
    __syncthreads();

    for (int it = 0; it < NPAIR; ++it) {
        int s = it & 1;
        int nxt = it + 1;
        bool have = nxt < NPAIR;
        uint32_t chb = 0;
        uint4 v0, v1, v2, v3;

        if (have) {
            if ((nxt & 3) == 0) tapsetup(nxt >> 2);
            chb = (uint32_t)((nxt & 3) * 64 + o8 * 8);
            v0 = *(const uint4*)(xh + ofs[0][0] + chb);
            v1 = *(const uint4*)(xh + ofs[0][1] + chb);
            v2 = *(const uint4*)(xh + ofs[0][2] + chb);
            v3 = *(const uint4*)(xh + ofs[0][3] + chb);
            cpasyncB(nxt, s ^ 1);
        }

        domma(s, 0);

        if (have) {
            combine_store(0, v0, v1, v2, v3, AsArr[s ^ 1]);
            v0 = *(const uint4*)(xh + ofs[1][0] + chb);
            v1 = *(const uint4*)(xh + ofs[1][1] + chb);
            v2 = *(const uint4*)(xh + ofs[1][2] + chb);
            v3 = *(const uint4*)(xh + ofs[1][3] + chb);
        }

        domma(s, 1);

        if (have) combine_store(1, v0, v1, v2, v3, AsArr[s ^ 1]);

        domma(s, 2);
        domma(s, 3);

        CP_WAIT0();
        __syncthreads();
    }

    // ---- epilogue: acc -> global with bias ----
    {
        int col0 = wn * 64;
        int qrow = lane >> 2;
        int qcol = (lane & 3) * 2;
        float2 bv[8];
#pragma unroll
        for (int nt = 0; nt < 8; ++nt)
            bv[nt] = *(const float2*)(bias + col0 + nt * 8 + qcol);
#pragma unroll
        for (int mt = 0; mt < 2; ++mt) {
            int row = tile0 + wm * 32 + mt * 16 + qrow;
#pragma unroll
            for (int nt = 0; nt < 8; ++nt) {
                int col = col0 + nt * 8 + qcol;
                float2 lo, hi;
                lo.x = acc[mt][nt][0] + bv[nt].x;
                lo.y = acc[mt][nt][1] + bv[nt].y;
                hi.x = acc[mt][nt][2] + bv[nt].x;
                hi.y = acc[mt][nt][3] + bv[nt].y;
                *(float2*)(out + (size_t)row * FF + col)       = lo;
                *(float2*)(out + (size_t)(row + 8) * FF + col) = hi;
            }
        }
    }
}

extern "C" void kernel_launch(void* const* d_in, const int* in_sizes, int n_in,
                              void* d_out, int out_size)
{
    const float* x    = (const float*)d_in[0];  // [4,96,96,256]
    const float* omk  = (const float*)d_in[1];  // [3,3,256,27]
    const float* omb  = (const float*)d_in[2];  // [27]
    const float* kern = (const float*)d_in[3];  // [2304,256]
    const float* bias = (const float*)d_in[4];  // [256]
    float* out = (float*)d_out;                 // [36864,256]

    cudaFuncSetAttribute(dcn_mma_kernel,
                         cudaFuncAttributeMaxDynamicSharedMemorySize, SMEM_U32 * 4);

    prep_kernel<<<5904, 256>>>((const float4*)x, kern, omk);
    om_mma_kernel<<<TOTPIX / 64, 128>>>(omb);
    dcn_mma_kernel<<<TOTPIX / 128, 512, SMEM_U32 * 4>>>(bias, out);
}

// round 14
// speedup vs baseline: 1.1311x; 1.0191x over previous
#include <cuda_runtime.h>
#include <cuda_fp16.h>
#include <math.h>
#include <stdint.h>

#define HH 96
#define WW 96
#define CC 256
#define FF 256
#define BB 4
#define NPIX (HH*WW)        // 9216
#define TOTPIX (BB*NPIX)    // 36864
#define NCHUNK 72           // 2304 / 32
#define NPAIR 36

// scratch: per (pixel, tap): (py, px, mask, 0)
__device__ float4 g_offmask[TOTPIX * 9];
// main weights fp16, n-pair merged: [chunk72][ks2][ntp16][lane32][ntq2][reg2]
__device__ uint32_t g_kernH[NCHUNK * 2 * 16 * 32 * 4];
// om weights fp16, n-pair merged: [chunk72][ks2][ntp2][lane32][ntq2][reg2] (n>=27 zero)
__device__ uint32_t g_omkH[NCHUNK * 2 * 2 * 32 * 4];
// fp16 copy of x (half2-packed in uint4 for alignment)
__device__ uint4 g_xh4[TOTPIX * CC / 8];

__device__ __forceinline__ uint32_t smem_u32(const void* p) {
    uint32_t a;
    asm("{ .reg .u64 t; cvta.to.shared.u64 t, %1; cvt.u32.u64 %0, t; }" : "=r"(a) : "l"(p));
    return a;
}

#define CP_ASYNC16(dst, src) \
    asm volatile("cp.async.cg.shared.global [%0], [%1], 16;" :: "r"(dst), "l"(src) : "memory")
#define CP_COMMIT() asm volatile("cp.async.commit_group;" ::: "memory")
#define CP_WAIT0()  asm volatile("cp.async.wait_group 0;" ::: "memory")

__device__ __forceinline__ void mma_f16(
    float* d, uint4 a, uint32_t b0, uint32_t b1)
{
    asm volatile(
        "mma.sync.aligned.m16n8k16.row.col.f32.f16.f16.f32 "
        "{%0,%1,%2,%3}, {%4,%5,%6,%7}, {%8,%9}, {%0,%1,%2,%3};"
        : "+f"(d[0]), "+f"(d[1]), "+f"(d[2]), "+f"(d[3])
        : "r"(a.x), "r"(a.y), "r"(a.z), "r"(a.w), "r"(b0), "r"(b1));
}

// ---------------------------------------------------------------------------
// Kernel 0: merged prep. Blocks [0,4608): x->fp16. [4608,5760): main weight
// pack (n-pair merged). [5760,5904): om weight pack (n-pair merged).
// ---------------------------------------------------------------------------
__global__ void __launch_bounds__(256) prep_kernel(
    const float4* __restrict__ x4, const float* __restrict__ kern,
    const float* __restrict__ omk)
{
    int blk = blockIdx.x;
    int tid = threadIdx.x;
    if (blk < 4608) {
        int idx = blk * 256 + tid;
        float4 a = x4[idx * 2];
        float4 b = x4[idx * 2 + 1];
        __half2 h0 = __floats2half2_rn(a.x, a.y);
        __half2 h1 = __floats2half2_rn(a.z, a.w);
        __half2 h2 = __floats2half2_rn(b.x, b.y);
        __half2 h3 = __floats2half2_rn(b.z, b.w);
        uint4 o;
        o.x = *(uint32_t*)&h0; o.y = *(uint32_t*)&h1;
        o.z = *(uint32_t*)&h2; o.w = *(uint32_t*)&h3;
        g_xh4[idx] = o;
    } else if (blk < 5760) {
        int idx = (blk - 4608) * 256 + tid;     // 0 .. 294911
        int reg  = idx & 1;
        int ntq  = (idx >> 1) & 1;
        int lane = (idx >> 2) & 31;
        int ntp  = (idx >> 7) & 15;
        int ks   = (idx >> 11) & 1;
        int c    = idx >> 12;
        int nt = ntp * 2 + ntq;
        int n = nt * 8 + (lane >> 2);
        int k = c * 32 + ks * 16 + (lane & 3) * 2 + reg * 8;
        __half2 h = __floats2half2_rn(kern[k * 256 + n], kern[(k + 1) * 256 + n]);
        g_kernH[idx] = *(uint32_t*)&h;
    } else {
        int idx = (blk - 5760) * 256 + tid;     // 0 .. 36863
        int reg  = idx & 1;
        int ntq  = (idx >> 1) & 1;
        int lane = (idx >> 2) & 31;
        int ntp  = (idx >> 7) & 1;
        int ks   = (idx >> 8) & 1;
        int c    = idx >> 9;
        int nt = ntp * 2 + ntq;
        int n = nt * 8 + (lane >> 2);
        int k = c * 32 + ks * 16 + (lane & 3) * 2 + reg * 8;
        float v0 = 0.f, v1 = 0.f;
        if (n < 27) {
            v0 = omk[k * 27 + n];
            v1 = omk[(k + 1) * 27 + n];
        }
        __half2 h = __floats2half2_rn(v0, v1);
        g_omkH[idx] = *(uint32_t*)&h;
    }
}

// ---------------------------------------------------------------------------
// Kernel 1: om conv fp16 HMMA. 576 CTAs x 128 threads, tile 64 px x 32 N.
// B fragments n-pair merged (uint4 per lane -> 2 nt).
// ---------------------------------------------------------------------------
__global__ void __launch_bounds__(128) om_mma_kernel(const float* __restrict__ omb)
{
    __shared__ uint32_t smA[2][2112];   // 16 blocks (4 amt x 4 ks) * 132
    __shared__ uint32_t smB[2][1024];   // 2 chunks * 512
    __shared__ float om_s[64 * 28];
    uint32_t sbB = smem_u32(&smB[0][0]);

    int tid  = threadIdx.x;
    int wid  = tid >> 5;
    int lane = tid & 31;

    int tile0 = blockIdx.x * 64;
    int b = tile0 / NPIX;
    const __half* xh = (const __half*)g_xh4 + (size_t)b * NPIX * CC;

    int o8  = lane & 7;
    int pxq = lane >> 3;
    int sks = o8 >> 1;

    int pxl[4];
    uint32_t ast[4];
    int hoq[4], woq[4];
#pragma unroll
    for (int q = 0; q < 4; ++q) {
        pxl[q] = wid * 16 + q * 4 + pxq;
        int r = pxl[q] & 15, amt = pxl[q] >> 4;
        ast[q] = (uint32_t)(amt * 4 + sks) * 132u
               + (uint32_t)((r & 7) * 16)
               + (uint32_t)((r >= 8) ? 1 : 0)
               + (uint32_t)((o8 & 1) ? 2 : 0);
        int pp = tile0 + pxl[q];
        hoq[q] = (pp % NPIX) / WW;
        woq[q] = pp % WW;
    }

    float acc[4][4];
#pragma unroll
    for (int j = 0; j < 4; ++j)
#pragma unroll
        for (int q = 0; q < 4; ++q) acc[j][q] = 0.f;

    uint32_t rofs[4];
    bool rval[4];

    auto tapsetup = [&](int tap) {
        int ky = tap / 3, kx = tap % 3;
#pragma unroll
        for (int q = 0; q < 4; ++q) {
            int y = hoq[q] - 1 + ky, xx = woq[q] - 1 + kx;
            rval[q] = (y >= 0 && y < HH && xx >= 0 && xx < WW);
            rofs[q] = (uint32_t)((y * WW + xx) * CC);
        }
    };

    auto cpasyncB = [&](int pr, int s) {
        const uint4* src = (const uint4*)g_omkH + (size_t)pr * 256;
        uint32_t bdst = sbB + (uint32_t)s * 4096;
        CP_ASYNC16(bdst + (uint32_t)tid * 16, (const void*)(src + tid));
        CP_ASYNC16(bdst + (uint32_t)(tid + 128) * 16, (const void*)(src + tid + 128));
        CP_COMMIT();
    };

    auto loadv = [&](int pr, uint4* v) {
        uint32_t chb = (uint32_t)((pr & 3) * 64 + o8 * 8);
#pragma unroll
        for (int q = 0; q < 4; ++q) {
            if (rval[q]) v[q] = *(const uint4*)(xh + rofs[q] + chb);
            else         v[q] = make_uint4(0u, 0u, 0u, 0u);
        }
    };

    auto storev = [&](int q, uint4 v, uint32_t* An) {
        An[ast[q]]      = v.x;
        An[ast[q] + 4]  = v.y;
        An[ast[q] + 8]  = v.z;
        An[ast[q] + 12] = v.w;
    };

    auto domma = [&](int s, int kss) {
        const uint32_t* As = smA[s];
        uint4 af = *(const uint4*)(As + (uint32_t)(wid * 4 + kss) * 132u + (uint32_t)lane * 4u);
        const uint32_t* Bc = smB[s] + (kss >> 1) * 512;
        int ks = kss & 1;
#pragma unroll
        for (int ntp = 0; ntp < 2; ++ntp) {
            uint4 bf = *(const uint4*)(Bc + ((uint32_t)((ks * 2 + ntp) * 32) + lane) * 4u);
            mma_f16(acc[ntp * 2],     af, bf.x, bf.y);
            mma_f16(acc[ntp * 2 + 1], af, bf.z, bf.w);
        }
    };

    // prologue: fill pair 0
    {
        tapsetup(0);
        uint4 v[4];
        loadv(0, v);
#pragma unroll
        for (int q = 0; q < 4; ++q) storev(q, v[q], smA[0]);
        cpasyncB(0, 0);
        CP_WAIT0();
        __syncthreads();
    }

    for (int it = 0; it < NPAIR; ++it) {
        int s = it & 1;
        int nxt = it + 1;
        bool have = nxt < NPAIR;
        uint4 v[4];
        if (have) {
            if ((nxt & 3) == 0) tapsetup(nxt >> 2);
            loadv(nxt, v);
            cpasyncB(nxt, s ^ 1);
        }
        domma(s, 0);
        if (have) { storev(0, v[0], smA[s ^ 1]); storev(1, v[1], smA[s ^ 1]); }
        domma(s, 1);
        if (have) { storev(2, v[2], smA[s ^ 1]); storev(3, v[3], smA[s ^ 1]); }
        domma(s, 2);
        domma(s, 3);
        CP_WAIT0();
        __syncthreads();
    }

    // ---- epilogue: acc (+bias) -> om_s ----
    {
        int qrow = lane >> 2;
        int qcol = (lane & 3) * 2;
        int row = wid * 16 + qrow;
#pragma unroll
        for (int nt = 0; nt < 4; ++nt) {
            int col = nt * 8 + qcol;
            if (col < 27) {
                float ob = omb[col];
                om_s[row * 28 + col]       = acc[nt][0] + ob;
                om_s[(row + 8) * 28 + col] = acc[nt][2] + ob;
            }
            if (col + 1 < 27) {
                float ob = omb[col + 1];
                om_s[row * 28 + col + 1]       = acc[nt][1] + ob;
                om_s[(row + 8) * 28 + col + 1] = acc[nt][3] + ob;
            }
        }
    }
    __syncthreads();

    // ---- offsets/mask -> g_offmask ----
    if (tid < 64) {
        int px = tid;
        int pp = tile0 + px;
        int ho = (pp % NPIX) / WW;
        int wo = pp % WW;
#pragma unroll
        for (int k = 0; k < 9; ++k) {
            float dy = om_s[px * 28 + 2 * k];
            float dx = om_s[px * 28 + 2 * k + 1];
            float m  = 2.f / (1.f + expf(-om_s[px * 28 + 18 + k]));
            int ky = k / 3, kx = k % 3;
            float py  = (float)(ho - 1 + ky) + dy;
            float pxx = (float)(wo - 1 + kx) + dx;
            g_offmask[pp * 9 + k] = make_float4(py, pxx, m, 0.f);
        }
    }
}

// ---------------------------------------------------------------------------
// Kernel 2: fused bilinear sampling (fp16 x) + HMMA fp16 GEMM, chunk-pair
// stages. 288 CTAs x 512 threads. B fragments n-pair merged.
// ---------------------------------------------------------------------------
#define A_STAGE 4224                 // u32: 32 blocks (8 amt x 4 ks) * 132
#define B_STAGE 8192                 // u32: 2 chunks * 16 KB
#define SMEM_U32 (2*A_STAGE + 2*B_STAGE)

__global__ void __launch_bounds__(512, 1) dcn_mma_kernel(
    const float* __restrict__ bias, float* __restrict__ out)
{
    extern __shared__ uint32_t sm[];
    uint32_t* AsArr[2] = { sm, sm + A_STAGE };
    uint32_t* BsArr[2] = { sm + 2*A_STAGE, sm + 2*A_STAGE + B_STAGE };
    uint32_t sbB = smem_u32(sm + 2*A_STAGE);

    int tid  = threadIdx.x;
    int wid  = tid >> 5;
    int lane = tid & 31;

    int tile0 = blockIdx.x * 128;
    int b = tile0 / NPIX;
    const __half* xh = (const __half*)g_xh4 + (size_t)b * NPIX * CC;

    int o8  = lane & 7;
    int pxq = lane >> 3;
    int pxl[2] = { wid * 8 + pxq, wid * 8 + 4 + pxq };
    int sks = o8 >> 1;

    uint32_t ast[2];
#pragma unroll
    for (int q = 0; q < 2; ++q) {
        int r   = pxl[q] & 15;
        int amt = pxl[q] >> 4;
        ast[q] = (uint32_t)(amt * 4 + sks) * 132u
               + (uint32_t)((r & 7) * 16)
               + (uint32_t)((r >= 8) ? 1 : 0)
               + (uint32_t)((o8 & 1) ? 2 : 0);
    }

    int wm = wid & 3;
    int wn = wid >> 2;

    float acc[2][8][4];
#pragma unroll
    for (int i = 0; i < 2; ++i)
#pragma unroll
        for (int j = 0; j < 8; ++j)
#pragma unroll
            for (int q = 0; q < 4; ++q) acc[i][j][q] = 0.f;

    float wgt[2][4];
    uint32_t ofs[2][4];

    auto tapsetup = [&](int tap) {
#pragma unroll
        for (int q = 0; q < 2; ++q) {
            float4 om = g_offmask[(size_t)(tile0 + pxl[q]) * 9 + tap];
            float fy0 = floorf(om.x), fx0 = floorf(om.y);
            int iy0 = (int)fy0, ix0 = (int)fx0;
            float fy = om.x - fy0, fx = om.y - fx0;
            float m = om.z;
            float w00 = (1.f - fy) * (1.f - fx) * m;
            float w01 = (1.f - fy) * fx * m;
            float w10 = fy * (1.f - fx) * m;
            float w11 = fy * fx * m;
            if (iy0 < 0  || iy0 >= HH)     { w00 = 0.f; w01 = 0.f; }
            if (iy0 < -1 || iy0 >= HH - 1) { w10 = 0.f; w11 = 0.f; }
            if (ix0 < 0  || ix0 >= WW)     { w00 = 0.f; w10 = 0.f; }
            if (ix0 < -1 || ix0 >= WW - 1) { w01 = 0.f; w11 = 0.f; }
            int y0c = min(max(iy0, 0), HH - 1);
            int y1c = min(max(iy0 + 1, 0), HH - 1);
            int x0c = min(max(ix0, 0), WW - 1);
            int x1c = min(max(ix0 + 1, 0), WW - 1);
            wgt[q][0] = w00; wgt[q][1] = w01; wgt[q][2] = w10; wgt[q][3] = w11;
            ofs[q][0] = (uint32_t)((y0c * WW + x0c) * CC);
            ofs[q][1] = (uint32_t)((y0c * WW + x1c) * CC);
            ofs[q][2] = (uint32_t)((y1c * WW + x0c) * CC);
            ofs[q][3] = (uint32_t)((y1c * WW + x1c) * CC);
        }
    };

    auto cpasyncB = [&](int pr, int s) {
        const float4* src = (const float4*)g_kernH + (size_t)pr * 2048;
        uint32_t bdst = sbB + (uint32_t)s * (B_STAGE * 4);
#pragma unroll
        for (int i = 0; i < 4; ++i)
            CP_ASYNC16(bdst + (uint32_t)(tid + i * 512) * 16,
                       (const void*)(src + tid + i * 512));
        CP_COMMIT();
    };

    auto combine_store = [&](int q, uint4 v0, uint4 v1, uint4 v2, uint4 v3,
                             uint32_t* An) {
        float r[8];
        const __half2* h0 = (const __half2*)&v0;
        const __half2* h1 = (const __half2*)&v1;
        const __half2* h2 = (const __half2*)&v2;
        const __half2* h3 = (const __half2*)&v3;
#pragma unroll
        for (int j = 0; j < 4; ++j) {
            float2 f0 = __half22float2(h0[j]);
            float2 f1 = __half22float2(h1[j]);
            float2 f2 = __half22float2(h2[j]);
            float2 f3 = __half22float2(h3[j]);
            r[2*j]   = wgt[q][0]*f0.x + wgt[q][1]*f1.x + wgt[q][2]*f2.x + wgt[q][3]*f3.x;
            r[2*j+1] = wgt[q][0]*f0.y + wgt[q][1]*f1.y + wgt[q][2]*f2.y + wgt[q][3]*f3.y;
        }
#pragma unroll
        for (int j = 0; j < 4; ++j) {
            __half2 h = __floats2half2_rn(r[2*j], r[2*j+1]);
            An[ast[q] + j * 4] = *(uint32_t*)&h;
        }
    };

    auto domma = [&](int s, int kss) {
        const uint32_t* As = AsArr[s];
        uint4 af[2];
#pragma unroll
        for (int mt = 0; mt < 2; ++mt) {
            int amt = wm * 2 + mt;
            af[mt] = *(const uint4*)(As + (uint32_t)(amt * 4 + kss) * 132u + (uint32_t)lane * 4u);
        }
        const uint32_t* Bc = BsArr[s] + (kss >> 1) * 4096;
        int ks = kss & 1;
#pragma unroll
        for (int ntp = 0; ntp < 4; ++ntp) {
            int ntpg = wn * 4 + ntp;   // global nt-pair (0..15)
            uint4 bf = *(const uint4*)(Bc + ((uint32_t)((ks * 16 + ntpg) * 32) + lane) * 4u);
            mma_f16(acc[0][ntp * 2],     af[0], bf.x, bf.y);
            mma_f16(acc[1][ntp * 2],     af[1], bf.x, bf.y);
            mma_f16(acc[0][ntp * 2 + 1], af[0], bf.z, bf.w);
            mma_f16(acc[1][ntp * 2 + 1], af[1], bf.z, bf.w);
        }
    };

    // prologue: fill pair 0
    tapsetup(0);
#pragma unroll
    for (int q = 0; q < 2; ++q) {
        uint32_t chb = (uint32_t)(o8 * 8);
        uint4 v0 = *(const uint4*)(xh + ofs[q][0] + chb);
        uint4 v1 = *(const uint4*)(xh + ofs[q][1] + chb);
        uint4 v2 = *(const uint4*)(xh + ofs[q][2] + chb);
        uint4 v3 = *(const uint4*)(xh + ofs[q][3] + chb);
        combine_store(q, v0, v1, v2, v3, AsArr[0]);
    }
    cpasyncB(0, 0);
    CP_WAIT0();
    __syncthreads();

    for (int it = 0; it < NPAIR; ++it) {
        int s = it & 1;
        int nxt = it + 1;
        bool have = nxt < NPAIR;
        uint32_t chb = 0;
        uint4 v0, v1, v2, v3;

        if (have) {
            if ((nxt & 3) == 0) tapsetup(nxt >> 2);
            chb = (uint32_t)((nxt & 3) * 64 + o8 * 8);
            v0 = *(const uint4*)(xh + ofs[0][0] + chb);
            v1 = *(const uint4*)(xh + ofs[0][1] + chb);
            v2 = *(const uint4*)(xh + ofs[0][2] + chb);
            v3 = *(const uint4*)(xh + ofs[0][3] + chb);
            cpasyncB(nxt, s ^ 1);
        }

        domma(s, 0);

        if (have) {
            combine_store(0, v0, v1, v2, v3, AsArr[s ^ 1]);
            v0 = *(const uint4*)(xh + ofs[1][0] + chb);
            v1 = *(const uint4*)(xh + ofs[1][1] + chb);
            v2 = *(const uint4*)(xh + ofs[1][2] + chb);
            v3 = *(const uint4*)(xh + ofs[1][3] + chb);
        }

        domma(s, 1);

        if (have) combine_store(1, v0, v1, v2, v3, AsArr[s ^ 1]);

        domma(s, 2);
        domma(s, 3);

        CP_WAIT0();
        __syncthreads();
    }

    // ---- epilogue: acc -> global with bias ----
    {
        int col0 = wn * 64;
        int qrow = lane >> 2;
        int qcol = (lane & 3) * 2;
        float2 bv[8];
#pragma unroll
        for (int nt = 0; nt < 8; ++nt)
            bv[nt] = *(const float2*)(bias + col0 + nt * 8 + qcol);
#pragma unroll
        for (int mt = 0; mt < 2; ++mt) {
            int row = tile0 + wm * 32 + mt * 16 + qrow;
#pragma unroll
            for (int nt = 0; nt < 8; ++nt) {
                int col = col0 + nt * 8 + qcol;
                float2 lo, hi;
                lo.x = acc[mt][nt][0] + bv[nt].x;
                lo.y = acc[mt][nt][1] + bv[nt].y;
                hi.x = acc[mt][nt][2] + bv[nt].x;
                hi.y = acc[mt][nt][3] + bv[nt].y;
                *(float2*)(out + (size_t)row * FF + col)       = lo;
                *(float2*)(out + (size_t)(row + 8) * FF + col) = hi;
            }
        }
    }
}

extern "C" void kernel_launch(void* const* d_in, const int* in_sizes, int n_in,
                              void* d_out, int out_size)
{
    const float* x    = (const float*)d_in[0];  // [4,96,96,256]
    const float* omk  = (const float*)d_in[1];  // [3,3,256,27]
    const float* omb  = (const float*)d_in[2];  // [27]
    const float* kern = (const float*)d_in[3];  // [2304,256]
    const float* bias = (const float*)d_in[4];  // [256]
    float* out = (float*)d_out;                 // [36864,256]

    cudaFuncSetAttribute(dcn_mma_kernel,
                         cudaFuncAttributeMaxDynamicSharedMemorySize, SMEM_U32 * 4);

    prep_kernel<<<5904, 256>>>((const float4*)x, kern, omk);
    om_mma_kernel<<<TOTPIX / 64, 128>>>(omb);
    dcn_mma_kernel<<<TOTPIX / 128, 512, SMEM_U32 * 4>>>(bias, out);
}